// round 2
// baseline (speedup 1.0000x reference)
#include <cuda_runtime.h>
#include <cuda_bf16.h>

// ---------------------------------------------------------------------------
// Differentiable JPEG, fused single kernel.
//   in : images [8,3,512,512] f32, q_y [8,8] f32, q_c [8,8] f32
//   out: [8,3,512,512] f32
// One CTA (192 threads) handles an 8x64 pixel tile = 8 blocks x 3 channels.
// ---------------------------------------------------------------------------

// DCT-II matrix entries, 0.5*cos(k*pi/16), matching the float32 cast of the
// reference's float64 construction. Expanded as a function-local constexpr
// (macro) so device code needs no --expt-relaxed-constexpr and ptxas folds
// entries into FFMA immediates.
#define DA0 0.35355339059327373f
#define DC1 0.49039264020161522f
#define DC2 0.46193976625564337f
#define DC3 0.41573480615127262f
#define DC4 0.35355339059327373f
#define DC5 0.27778511650980114f
#define DC6 0.19134171618254492f
#define DC7 0.097545161008064166f

#define DCT_INIT {                                                  \
    {  DA0,  DA0,  DA0,  DA0,  DA0,  DA0,  DA0,  DA0 },             \
    {  DC1,  DC3,  DC5,  DC7, -DC7, -DC5, -DC3, -DC1 },             \
    {  DC2,  DC6, -DC6, -DC2, -DC2, -DC6,  DC6,  DC2 },             \
    {  DC3, -DC7, -DC1, -DC5,  DC5,  DC1,  DC7, -DC3 },             \
    {  DC4, -DC4, -DC4,  DC4,  DC4, -DC4, -DC4,  DC4 },             \
    {  DC5, -DC1,  DC7,  DC3, -DC3, -DC7,  DC1, -DC5 },             \
    {  DC6, -DC2,  DC2, -DC6, -DC6,  DC2, -DC2,  DC6 },             \
    {  DC7, -DC5,  DC3, -DC1,  DC1, -DC3,  DC5, -DC7 },             \
}

// soft_round(x) = -10 + sum_{k=-10}^{9} sigmoid(50*(x - k - 0.5))
// With TEMP=50, every term with |arg| >= 25 saturates to fp32-exact 0/1.
// Only ONE term is ever in transition: count the saturated ones analytically,
// evaluate exactly one sigmoid.
__device__ __forceinline__ float soft_round_fast(float f) {
    float kc  = floorf(f - 0.5f);                       // f - kc in [0.5, 1.5)
    float cnt = fminf(fmaxf(kc + 10.0f, 0.0f), 20.0f);  // #terms k<=kc-1 in range
    float g   = (f - kc - 0.5f) * 50.0f;                // [0, 50)
    bool  hi  = g > 25.0f;
    float h     = hi ? g - 50.0f : g;                   // transition term arg
    float kterm = hi ? kc + 1.0f : kc;                  // which k it belongs to
    float extra = (hi && kc >= -10.0f && kc <= 9.0f) ? 1.0f : 0.0f;
    float e = __expf(-h);                               // h in [-25,25]
    float s = __fdividef(1.0f, 1.0f + e);
    if (kterm < -10.0f || kterm > 9.0f) s = 0.0f;
    return (cnt - 10.0f) + extra + s;
}

__global__ void __launch_bounds__(192)
djpeg_kernel(const float* __restrict__ img,
             const float* __restrict__ qy,
             const float* __restrict__ qc,
             float* __restrict__ out)
{
    constexpr float DM[8][8] = DCT_INIT;

    __shared__ float s_p[3][512];        // [ch][row*64 + col] YCbCr tile / rec tile
    __shared__ float s_scr[24 * 72];     // [cb][i*9 + k], pad 9 -> conflict-free transpose
    __shared__ float s_qt[2][64];        // clipped quant tables (y, chroma)
    __shared__ float s_rq[2][64];        // reciprocals

    const int t    = threadIdx.x;
    const int bimg = blockIdx.z;
    const int row0 = blockIdx.y << 3;    // 8-row band
    const int col0 = blockIdx.x << 6;    // 64-col band

    // quant tables: clip to [2,15], precompute reciprocal
    if (t < 128) {
        int chq = t >> 6, idx = t & 63;
        float v = chq ? qc[idx] : qy[idx];
        v = fminf(fmaxf(v, 2.0f), 15.0f);
        s_qt[chq][idx] = v;
        s_rq[chq][idx] = 1.0f / v;
    }

    const size_t plane = 512 * 512;
    const float* base = img + (size_t)bimg * 3 * plane + (size_t)row0 * 512 + col0;

    // ---- load + forward color transform (coalesced along W) ----
    for (int idx = t; idx < 512; idx += 192) {
        int rr = idx >> 6, cc = idx & 63;
        size_t off = (size_t)rr * 512 + cc;
        float r  = __saturatef(base[off]);
        float g  = __saturatef(base[plane + off]);
        float bl = __saturatef(base[2 * plane + off]);
        s_p[0][idx] =  0.299f    * r + 0.587f    * g + 0.114f    * bl;
        s_p[1][idx] = -0.168736f * r - 0.331264f * g + 0.5f      * bl + 0.5f;
        s_p[2][idx] =  0.5f      * r - 0.418688f * g - 0.081312f * bl + 0.5f;
    }
    __syncthreads();

    const int cb = t >> 3;        // channel-block 0..23
    const int ch = cb >> 3;       // 0..2
    const int bc = cb & 7;        // block column within tile
    const int q  = t & 7;         // lane role: column (stages A/D) or row (B/C)

    // ---- stage A: M = D * B (column-local) ----
    {
        float x[8];
        #pragma unroll
        for (int j = 0; j < 8; j++) x[j] = s_p[ch][j * 64 + bc * 8 + q];
        #pragma unroll
        for (int i = 0; i < 8; i++) {
            float acc = DM[i][0] * x[0];
            #pragma unroll
            for (int j = 1; j < 8; j++) acc += DM[i][j] * x[j];
            s_scr[cb * 72 + i * 9 + q] = acc;    // M[i][q]
        }
    }
    __syncthreads();

    // ---- stage B: coef = M * D (row-local), quant, stage C: N = Q * D^T ----
    {
        const int i = q;                          // this thread owns row i
        float mr[8];
        #pragma unroll
        for (int k = 0; k < 8; k++) mr[k] = s_scr[cb * 72 + i * 9 + k];

        const int qs = (ch == 0) ? 0 : 1;
        float qv[8];
        #pragma unroll
        for (int l = 0; l < 8; l++) {
            float c = DM[0][l] * mr[0];
            #pragma unroll
            for (int k = 1; k < 8; k++) c += DM[k][l] * mr[k];
            float f = c * s_rq[qs][i * 8 + l];
            qv[l] = soft_round_fast(f) * s_qt[qs][i * 8 + l];
        }
        // N[i][b] = sum_l Q[i][l] * D[b][l]   (same thread, same row addresses)
        #pragma unroll
        for (int b2 = 0; b2 < 8; b2++) {
            float acc = qv[0] * DM[b2][0];
            #pragma unroll
            for (int l = 1; l < 8; l++) acc += qv[l] * DM[b2][l];
            s_scr[cb * 72 + i * 9 + b2] = acc;
        }
    }
    __syncthreads();

    // ---- stage D: rec = D^T * N (column-local) ----
    {
        float nc[8];
        #pragma unroll
        for (int i = 0; i < 8; i++) nc[i] = s_scr[cb * 72 + i * 9 + q];
        #pragma unroll
        for (int a = 0; a < 8; a++) {
            float acc = DM[0][a] * nc[0];
            #pragma unroll
            for (int i = 1; i < 8; i++) acc += DM[i][a] * nc[i];
            s_p[ch][a * 64 + bc * 8 + q] = acc;
        }
    }
    __syncthreads();

    // ---- inverse color transform + store (coalesced) ----
    float* obase = out + (size_t)bimg * 3 * plane + (size_t)row0 * 512 + col0;
    for (int idx = t; idx < 512; idx += 192) {
        int rr = idx >> 6, cc = idx & 63;
        size_t off = (size_t)rr * 512 + cc;
        float y   = s_p[0][idx];
        float cbv = s_p[1][idx] - 0.5f;
        float crv = s_p[2][idx] - 0.5f;
        float r2 = y + 1.402f * crv;
        float g2 = y - 0.344136f * cbv - 0.714136f * crv;
        float b2 = y + 1.772f * cbv;
        obase[off]             = __saturatef(r2);
        obase[plane + off]     = __saturatef(g2);
        obase[2 * plane + off] = __saturatef(b2);
    }
}

extern "C" void kernel_launch(void* const* d_in, const int* in_sizes, int n_in,
                              void* d_out, int out_size) {
    const float* img = (const float*)d_in[0];
    const float* qy  = (const float*)d_in[1];
    const float* qc  = (const float*)d_in[2];
    float* out = (float*)d_out;
    (void)in_sizes; (void)n_in; (void)out_size;

    dim3 grid(512 / 64, 512 / 8, 8);   // (W bands, H bands, batch)
    dim3 block(192);
    djpeg_kernel<<<grid, block>>>(img, qy, qc, out);
}

// round 6
// speedup vs baseline: 1.1357x; 1.1357x over previous
#include <cuda_runtime.h>
#include <cuda_bf16.h>

// ---------------------------------------------------------------------------
// Differentiable JPEG, fused. One thread owns a full 8x8 block in registers.
// CTA = 96 threads = 32 spatial blocks x 3 channels, tile = 8 rows x 256 cols.
// Grid = (2, 64, 8).
// ---------------------------------------------------------------------------

#define DA0 0.35355339059327373f
#define DC1 0.49039264020161522f
#define DC2 0.46193976625564337f
#define DC3 0.41573480615127262f
#define DC4 0.35355339059327373f
#define DC5 0.27778511650980114f
#define DC6 0.19134171618254492f
#define DC7 0.097545161008064166f

// forward: y = D x   (even/odd butterfly, 36 ops)
__device__ __forceinline__ void dct_fwd(float& x0, float& x1, float& x2, float& x3,
                                        float& x4, float& x5, float& x6, float& x7) {
    float e0 = x0 + x7, e1 = x1 + x6, e2 = x2 + x5, e3 = x3 + x4;
    float o0 = x0 - x7, o1 = x1 - x6, o2 = x2 - x5, o3 = x3 - x4;
    float ee0 = e0 + e3, ee1 = e1 + e2, eo0 = e0 - e3, eo1 = e1 - e2;
    float y0 = DA0 * (ee0 + ee1);
    float y4 = DC4 * (ee0 - ee1);
    float y2 = DC2 * eo0 + DC6 * eo1;
    float y6 = DC6 * eo0 - DC2 * eo1;
    float y1 = DC1 * o0 + DC3 * o1 + DC5 * o2 + DC7 * o3;
    float y3 = DC3 * o0 - DC7 * o1 - DC1 * o2 - DC5 * o3;
    float y5 = DC5 * o0 - DC1 * o1 + DC7 * o2 + DC3 * o3;
    float y7 = DC7 * o0 - DC5 * o1 + DC3 * o2 - DC1 * o3;
    x0 = y0; x1 = y1; x2 = y2; x3 = y3; x4 = y4; x5 = y5; x6 = y6; x7 = y7;
}

// inverse-type: z = D^T y  (36 ops)
__device__ __forceinline__ void dct_inv(float& y0, float& y1, float& y2, float& y3,
                                        float& y4, float& y5, float& y6, float& y7) {
    float t0 = DA0 * y0, t4 = DC4 * y4;
    float a = t0 + t4, b = t0 - t4;
    float c = DC2 * y2 + DC6 * y6;
    float d = DC6 * y2 - DC2 * y6;
    float E0 = a + c, E1 = b + d, E2 = b - d, E3 = a - c;
    float O0 = DC1 * y1 + DC3 * y3 + DC5 * y5 + DC7 * y7;
    float O1 = DC3 * y1 - DC7 * y3 - DC1 * y5 - DC5 * y7;
    float O2 = DC5 * y1 - DC1 * y3 + DC7 * y5 + DC3 * y7;
    float O3 = DC7 * y1 - DC5 * y3 + DC3 * y5 - DC1 * y7;
    y0 = E0 + O0; y7 = E0 - O0;
    y1 = E1 + O1; y6 = E1 - O1;
    y2 = E2 + O2; y5 = E2 - O2;
    y3 = E3 + O3; y4 = E3 - O3;
}

// block-major padded smem: [ch][block 0..31][76 words]; word = bc*76 + r*8 + j
#define BLK_STRIDE 76
#define CH_STRIDE  (32 * BLK_STRIDE)

__global__ void __launch_bounds__(96, 5)
djpeg_kernel(const float* __restrict__ img,
             const float* __restrict__ qy,
             const float* __restrict__ qc,
             float* __restrict__ out)
{
    __shared__ float s_pix[3 * CH_STRIDE];
    __shared__ float s_qt[2][64];
    __shared__ float s_rq[2][64];

    const int t    = threadIdx.x;
    const int bimg = blockIdx.z;
    const int row0 = blockIdx.y << 3;    // 8-row band
    const int col0 = blockIdx.x << 8;    // 256-col band

    // quant tables: clip to [2,15], reciprocals
    for (int i = t; i < 128; i += 96) {
        int chq = i >> 6, idx = i & 63;
        float v = chq ? qc[idx] : qy[idx];
        v = fminf(fmaxf(v, 2.0f), 15.0f);
        s_qt[chq][idx] = v;
        s_rq[chq][idx] = 1.0f / v;
    }

    const size_t plane = 512 * 512;
    const float* base = img + (size_t)bimg * 3 * plane + (size_t)row0 * 512 + col0;

    // ---- load + forward color transform, float4, into block-major smem ----
    for (int idx = t; idx < 512; idx += 96) {
        int rr = idx >> 6, c4 = idx & 63;
        const float4 r4 = *(const float4*)(base + (size_t)rr * 512 + c4 * 4);
        const float4 g4 = *(const float4*)(base + plane + (size_t)rr * 512 + c4 * 4);
        const float4 b4 = *(const float4*)(base + 2 * plane + (size_t)rr * 512 + c4 * 4);
        float4 yv, cbv, crv;
        {
            float r = __saturatef(r4.x), g = __saturatef(g4.x), bl = __saturatef(b4.x);
            yv.x  =  0.299f * r + 0.587f * g + 0.114f * bl;
            cbv.x = -0.168736f * r - 0.331264f * g + 0.5f * bl + 0.5f;
            crv.x =  0.5f * r - 0.418688f * g - 0.081312f * bl + 0.5f;
        }
        {
            float r = __saturatef(r4.y), g = __saturatef(g4.y), bl = __saturatef(b4.y);
            yv.y  =  0.299f * r + 0.587f * g + 0.114f * bl;
            cbv.y = -0.168736f * r - 0.331264f * g + 0.5f * bl + 0.5f;
            crv.y =  0.5f * r - 0.418688f * g - 0.081312f * bl + 0.5f;
        }
        {
            float r = __saturatef(r4.z), g = __saturatef(g4.z), bl = __saturatef(b4.z);
            yv.z  =  0.299f * r + 0.587f * g + 0.114f * bl;
            cbv.z = -0.168736f * r - 0.331264f * g + 0.5f * bl + 0.5f;
            crv.z =  0.5f * r - 0.418688f * g - 0.081312f * bl + 0.5f;
        }
        {
            float r = __saturatef(r4.w), g = __saturatef(g4.w), bl = __saturatef(b4.w);
            yv.w  =  0.299f * r + 0.587f * g + 0.114f * bl;
            cbv.w = -0.168736f * r - 0.331264f * g + 0.5f * bl + 0.5f;
            crv.w =  0.5f * r - 0.418688f * g - 0.081312f * bl + 0.5f;
        }
        int w = (c4 >> 1) * BLK_STRIDE + rr * 8 + (c4 & 1) * 4;  // block-major word
        *(float4*)&s_pix[w]                 = yv;
        *(float4*)&s_pix[CH_STRIDE + w]     = cbv;
        *(float4*)&s_pix[2 * CH_STRIDE + w] = crv;
    }
    __syncthreads();

    // ---- per-thread 8x8 block: thread t -> ch = t>>5, bc = t&31 ----
    {
        const int ch = t >> 5;
        const int bc = t & 31;
        const int qs = (ch == 0) ? 0 : 1;
        float* blkp = &s_pix[ch * CH_STRIDE + bc * BLK_STRIDE];

        float b[8][8];
        #pragma unroll
        for (int r = 0; r < 8; r++) {
            float4 lo = *(const float4*)(blkp + r * 8);
            float4 hi = *(const float4*)(blkp + r * 8 + 4);
            b[r][0] = lo.x; b[r][1] = lo.y; b[r][2] = lo.z; b[r][3] = lo.w;
            b[r][4] = hi.x; b[r][5] = hi.y; b[r][6] = hi.z; b[r][7] = hi.w;
        }

        // stage A: columns, forward (M = D * B)
        #pragma unroll
        for (int j = 0; j < 8; j++)
            dct_fwd(b[0][j], b[1][j], b[2][j], b[3][j], b[4][j], b[5][j], b[6][j], b[7][j]);

        // rows: coef = M*D (D^T-type), quant, N = Q*D^T (D-type)
        #pragma unroll
        for (int i = 0; i < 8; i++) {
            dct_inv(b[i][0], b[i][1], b[i][2], b[i][3], b[i][4], b[i][5], b[i][6], b[i][7]);

            float4 rqlo = *(const float4*)&s_rq[qs][i * 8];
            float4 rqhi = *(const float4*)&s_rq[qs][i * 8 + 4];
            float4 qtlo = *(const float4*)&s_qt[qs][i * 8];
            float4 qthi = *(const float4*)&s_qt[qs][i * 8 + 4];
            float rq[8] = {rqlo.x, rqlo.y, rqlo.z, rqlo.w, rqhi.x, rqhi.y, rqhi.z, rqhi.w};
            float qt[8] = {qtlo.x, qtlo.y, qtlo.z, qtlo.w, qthi.x, qthi.y, qthi.z, qthi.w};

            float basev[8], t1[8];
            #pragma unroll
            for (int l = 0; l < 8; l++) {
                float f  = b[i][l] * rq[l];
                float kc = floorf(f - 0.5f);
                float g  = (f - kc - 0.5f) * 50.0f;             // in [0,50)
                bool  hi = g > 25.0f;
                float h  = hi ? g - 50.0f : g;                  // transition arg in (-25,25]
                float hc = fminf(fmaxf(h, -13.6f), 13.6f);
                t1[l]    = 1.0f + __expf(-hc);                  // 1 + e^{-h}
                basev[l] = hi ? kc + 1.0f : kc;
            }
            // batched reciprocal: 1 RCP per 4 sigmoids
            #pragma unroll
            for (int g = 0; g < 2; g++) {
                float a = t1[g*4+0], b2 = t1[g*4+1], c = t1[g*4+2], d = t1[g*4+3];
                float pab = a * b2, pcd = c * d;
                float r  = __fdividef(1.0f, pab * pcd);
                float s0 = r * (b2 * pcd);
                float s1 = r * (a * pcd);
                float s2 = r * (pab * d);
                float s3 = r * (pab * c);
                b[i][g*4+0] = (basev[g*4+0] + s0) * qt[g*4+0];
                b[i][g*4+1] = (basev[g*4+1] + s1) * qt[g*4+1];
                b[i][g*4+2] = (basev[g*4+2] + s2) * qt[g*4+2];
                b[i][g*4+3] = (basev[g*4+3] + s3) * qt[g*4+3];
            }

            dct_fwd(b[i][0], b[i][1], b[i][2], b[i][3], b[i][4], b[i][5], b[i][6], b[i][7]);
        }

        // stage D: columns, inverse (rec = D^T * N)
        #pragma unroll
        for (int j = 0; j < 8; j++)
            dct_inv(b[0][j], b[1][j], b[2][j], b[3][j], b[4][j], b[5][j], b[6][j], b[7][j]);

        // write back
        #pragma unroll
        for (int r = 0; r < 8; r++) {
            float4 lo = make_float4(b[r][0], b[r][1], b[r][2], b[r][3]);
            float4 hi = make_float4(b[r][4], b[r][5], b[r][6], b[r][7]);
            *(float4*)(blkp + r * 8)     = lo;
            *(float4*)(blkp + r * 8 + 4) = hi;
        }
    }
    __syncthreads();

    // ---- inverse color transform + store, float4 ----
    float* obase = out + (size_t)bimg * 3 * plane + (size_t)row0 * 512 + col0;
    for (int idx = t; idx < 512; idx += 96) {
        int rr = idx >> 6, c4 = idx & 63;
        int w = (c4 >> 1) * BLK_STRIDE + rr * 8 + (c4 & 1) * 4;
        float4 yv  = *(const float4*)&s_pix[w];
        float4 cbv = *(const float4*)&s_pix[CH_STRIDE + w];
        float4 crv = *(const float4*)&s_pix[2 * CH_STRIDE + w];
        float4 r4, g4, b4;
        {
            float y = yv.x, cb = cbv.x - 0.5f, cr = crv.x - 0.5f;
            r4.x = __saturatef(y + 1.402f * cr);
            g4.x = __saturatef(y - 0.344136f * cb - 0.714136f * cr);
            b4.x = __saturatef(y + 1.772f * cb);
        }
        {
            float y = yv.y, cb = cbv.y - 0.5f, cr = crv.y - 0.5f;
            r4.y = __saturatef(y + 1.402f * cr);
            g4.y = __saturatef(y - 0.344136f * cb - 0.714136f * cr);
            b4.y = __saturatef(y + 1.772f * cb);
        }
        {
            float y = yv.z, cb = cbv.z - 0.5f, cr = crv.z - 0.5f;
            r4.z = __saturatef(y + 1.402f * cr);
            g4.z = __saturatef(y - 0.344136f * cb - 0.714136f * cr);
            b4.z = __saturatef(y + 1.772f * cb);
        }
        {
            float y = yv.w, cb = cbv.w - 0.5f, cr = crv.w - 0.5f;
            r4.w = __saturatef(y + 1.402f * cr);
            g4.w = __saturatef(y - 0.344136f * cb - 0.714136f * cr);
            b4.w = __saturatef(y + 1.772f * cb);
        }
        size_t off = (size_t)rr * 512 + c4 * 4;
        *(float4*)(obase + off)             = r4;
        *(float4*)(obase + plane + off)     = g4;
        *(float4*)(obase + 2 * plane + off) = b4;
    }
}

extern "C" void kernel_launch(void* const* d_in, const int* in_sizes, int n_in,
                              void* d_out, int out_size) {
    const float* img = (const float*)d_in[0];
    const float* qy  = (const float*)d_in[1];
    const float* qc  = (const float*)d_in[2];
    float* out = (float*)d_out;
    (void)in_sizes; (void)n_in; (void)out_size;

    dim3 grid(512 / 256, 512 / 8, 8);   // (W bands, H bands, batch)
    dim3 block(96);
    djpeg_kernel<<<grid, block>>>(img, qy, qc, out);
}

// round 10
// speedup vs baseline: 1.3023x; 1.1467x over previous
#include <cuda_runtime.h>
#include <cuda_bf16.h>

// ---------------------------------------------------------------------------
// Differentiable JPEG, fused. A lane PAIR owns one 8x8 block (32 floats/thread)
// to double occupancy vs the 1-thread-per-block variant (regs 128 -> ~80).
// CTA = 192 threads = 96 channel-blocks = 32 spatial blocks x 3 channels.
// Tile = 8 rows x 256 cols. Grid = (2, 64, 8).
// Orientation switches (column-halves <-> row-halves) via SHFL.XOR(1).
// ---------------------------------------------------------------------------

#define DA0 0.35355339059327373f
#define DC1 0.49039264020161522f
#define DC2 0.46193976625564337f
#define DC3 0.41573480615127262f
#define DC4 0.35355339059327373f
#define DC5 0.27778511650980114f
#define DC6 0.19134171618254492f
#define DC7 0.097545161008064166f

// forward: y = D x   (even/odd butterfly, 36 ops)
__device__ __forceinline__ void dct_fwd(float& x0, float& x1, float& x2, float& x3,
                                        float& x4, float& x5, float& x6, float& x7) {
    float e0 = x0 + x7, e1 = x1 + x6, e2 = x2 + x5, e3 = x3 + x4;
    float o0 = x0 - x7, o1 = x1 - x6, o2 = x2 - x5, o3 = x3 - x4;
    float ee0 = e0 + e3, ee1 = e1 + e2, eo0 = e0 - e3, eo1 = e1 - e2;
    float y0 = DA0 * (ee0 + ee1);
    float y4 = DC4 * (ee0 - ee1);
    float y2 = DC2 * eo0 + DC6 * eo1;
    float y6 = DC6 * eo0 - DC2 * eo1;
    float y1 = DC1 * o0 + DC3 * o1 + DC5 * o2 + DC7 * o3;
    float y3 = DC3 * o0 - DC7 * o1 - DC1 * o2 - DC5 * o3;
    float y5 = DC5 * o0 - DC1 * o1 + DC7 * o2 + DC3 * o3;
    float y7 = DC7 * o0 - DC5 * o1 + DC3 * o2 - DC1 * o3;
    x0 = y0; x1 = y1; x2 = y2; x3 = y3; x4 = y4; x5 = y5; x6 = y6; x7 = y7;
}

// inverse-type: z = D^T y  (36 ops)
__device__ __forceinline__ void dct_inv(float& y0, float& y1, float& y2, float& y3,
                                        float& y4, float& y5, float& y6, float& y7) {
    float t0 = DA0 * y0, t4 = DC4 * y4;
    float a = t0 + t4, b = t0 - t4;
    float c = DC2 * y2 + DC6 * y6;
    float d = DC6 * y2 - DC2 * y6;
    float E0 = a + c, E1 = b + d, E2 = b - d, E3 = a - c;
    float O0 = DC1 * y1 + DC3 * y3 + DC5 * y5 + DC7 * y7;
    float O1 = DC3 * y1 - DC7 * y3 - DC1 * y5 - DC5 * y7;
    float O2 = DC5 * y1 - DC1 * y3 + DC7 * y5 + DC3 * y7;
    float O3 = DC7 * y1 - DC5 * y3 + DC3 * y5 - DC1 * y7;
    y0 = E0 + O0; y7 = E0 - O0;
    y1 = E1 + O1; y6 = E1 - O1;
    y2 = E2 + O2; y5 = E2 - O2;
    y3 = E3 + O3; y4 = E3 - O3;
}

// block-major padded smem: [ch][block 0..31][72 words]; word = bc*72 + r*8 + j
// stride 72: pair-halved float4 accesses hit offsets {0,4,8,...,28} mod 32.
#define BLK_STRIDE 72
#define CH_STRIDE  (32 * BLK_STRIDE)

__global__ void __launch_bounds__(192, 4)
djpeg_kernel(const float* __restrict__ img,
             const float* __restrict__ qy,
             const float* __restrict__ qc,
             float* __restrict__ out)
{
    __shared__ float s_pix[3 * CH_STRIDE];
    __shared__ float s_qt[2][64];
    __shared__ float s_rq[2][64];

    const int t    = threadIdx.x;
    const int bimg = blockIdx.z;
    const int row0 = blockIdx.y << 3;    // 8-row band
    const int col0 = blockIdx.x << 8;    // 256-col band

    // quant tables: clip to [2,15], reciprocals
    if (t < 128) {
        int chq = t >> 6, idx = t & 63;
        float v = chq ? qc[idx] : qy[idx];
        v = fminf(fmaxf(v, 2.0f), 15.0f);
        s_qt[chq][idx] = v;
        s_rq[chq][idx] = 1.0f / v;
    }

    const size_t plane = 512 * 512;
    const float* base = img + (size_t)bimg * 3 * plane + (size_t)row0 * 512 + col0;

    // ---- load + forward color transform, float4, into block-major smem ----
    for (int idx = t; idx < 512; idx += 192) {
        int rr = idx >> 6, c4 = idx & 63;
        const float4 r4 = *(const float4*)(base + (size_t)rr * 512 + c4 * 4);
        const float4 g4 = *(const float4*)(base + plane + (size_t)rr * 512 + c4 * 4);
        const float4 b4 = *(const float4*)(base + 2 * plane + (size_t)rr * 512 + c4 * 4);
        float4 yv, cbv, crv;
        {
            float r = __saturatef(r4.x), g = __saturatef(g4.x), bl = __saturatef(b4.x);
            yv.x  =  0.299f * r + 0.587f * g + 0.114f * bl;
            cbv.x = -0.168736f * r - 0.331264f * g + 0.5f * bl + 0.5f;
            crv.x =  0.5f * r - 0.418688f * g - 0.081312f * bl + 0.5f;
        }
        {
            float r = __saturatef(r4.y), g = __saturatef(g4.y), bl = __saturatef(b4.y);
            yv.y  =  0.299f * r + 0.587f * g + 0.114f * bl;
            cbv.y = -0.168736f * r - 0.331264f * g + 0.5f * bl + 0.5f;
            crv.y =  0.5f * r - 0.418688f * g - 0.081312f * bl + 0.5f;
        }
        {
            float r = __saturatef(r4.z), g = __saturatef(g4.z), bl = __saturatef(b4.z);
            yv.z  =  0.299f * r + 0.587f * g + 0.114f * bl;
            cbv.z = -0.168736f * r - 0.331264f * g + 0.5f * bl + 0.5f;
            crv.z =  0.5f * r - 0.418688f * g - 0.081312f * bl + 0.5f;
        }
        {
            float r = __saturatef(r4.w), g = __saturatef(g4.w), bl = __saturatef(b4.w);
            yv.w  =  0.299f * r + 0.587f * g + 0.114f * bl;
            cbv.w = -0.168736f * r - 0.331264f * g + 0.5f * bl + 0.5f;
            crv.w =  0.5f * r - 0.418688f * g - 0.081312f * bl + 0.5f;
        }
        int w = (c4 >> 1) * BLK_STRIDE + rr * 8 + (c4 & 1) * 4;  // block-major word
        *(float4*)&s_pix[w]                 = yv;
        *(float4*)&s_pix[CH_STRIDE + w]     = cbv;
        *(float4*)&s_pix[2 * CH_STRIDE + w] = crv;
    }
    __syncthreads();

    // ---- pair-of-threads per 8x8 block ----
    {
        const int pb   = t >> 1;        // channel-block 0..95
        const int half = t & 1;         // which 4-col / 4-row half
        const int ch   = pb >> 5;       // 0..2
        const int bc   = pb & 31;
        const int qs   = (ch == 0) ? 0 : 1;
        const bool hodd = (half != 0);
        float* blkp = &s_pix[ch * CH_STRIDE + bc * BLK_STRIDE];

        // load my 4 columns (global cols half*4 .. half*4+3), all 8 rows
        float x[8][4];
        #pragma unroll
        for (int r = 0; r < 8; r++) {
            float4 v = *(const float4*)(blkp + r * 8 + half * 4);
            x[r][0] = v.x; x[r][1] = v.y; x[r][2] = v.z; x[r][3] = v.w;
        }

        // stage A: column forward DCT (local)
        #pragma unroll
        for (int c = 0; c < 4; c++)
            dct_fwd(x[0][c], x[1][c], x[2][c], x[3][c],
                    x[4][c], x[5][c], x[6][c], x[7][c]);

        // exchange -> row orientation: I own global rows half*4..half*4+3, all 8 cols
        float y[4][8];
        #pragma unroll
        for (int rr = 0; rr < 4; rr++) {
            #pragma unroll
            for (int c = 0; c < 4; c++) {
                float send = hodd ? x[rr][c] : x[rr + 4][c];
                float recv = __shfl_xor_sync(0xFFFFFFFFu, send, 1);
                y[rr][c]     = hodd ? recv        : x[rr][c];
                y[rr][4 + c] = hodd ? x[rr + 4][c] : recv;
            }
        }

        // row stages: coef = M*D (D^T-type), quant, N = Q*D^T (D-type)
        const int ibase = half * 4;
        #pragma unroll
        for (int rr = 0; rr < 4; rr++) {
            dct_inv(y[rr][0], y[rr][1], y[rr][2], y[rr][3],
                    y[rr][4], y[rr][5], y[rr][6], y[rr][7]);

            const int i = ibase + rr;
            float4 rqlo = *(const float4*)&s_rq[qs][i * 8];
            float4 rqhi = *(const float4*)&s_rq[qs][i * 8 + 4];
            float4 qtlo = *(const float4*)&s_qt[qs][i * 8];
            float4 qthi = *(const float4*)&s_qt[qs][i * 8 + 4];
            float rq[8] = {rqlo.x, rqlo.y, rqlo.z, rqlo.w, rqhi.x, rqhi.y, rqhi.z, rqhi.w};
            float qt[8] = {qtlo.x, qtlo.y, qtlo.z, qtlo.w, qthi.x, qthi.y, qthi.z, qthi.w};

            float basev[8], t1[8];
            #pragma unroll
            for (int l = 0; l < 8; l++) {
                float f  = y[rr][l] * rq[l];
                float kc = floorf(f - 0.5f);
                float g  = (f - kc - 0.5f) * 50.0f;             // in [0,50)
                bool  hi = g > 25.0f;
                float h  = hi ? g - 50.0f : g;                  // transition arg in (-25,25]
                float hc = fminf(fmaxf(h, -20.0f), 20.0f);
                t1[l]    = 1.0f + __expf(-hc);                  // 1 + e^{-h}
                basev[l] = hi ? kc + 1.0f : kc;
            }
            // batched reciprocal: 1 RCP per 4 sigmoids (P <= (1+e^20)^4 ~ 5.5e34, safe)
            #pragma unroll
            for (int g = 0; g < 2; g++) {
                float a = t1[g*4+0], b2 = t1[g*4+1], c = t1[g*4+2], d = t1[g*4+3];
                float pab = a * b2, pcd = c * d;
                float r  = __fdividef(1.0f, pab * pcd);
                float s0 = r * (b2 * pcd);
                float s1 = r * (a * pcd);
                float s2 = r * (pab * d);
                float s3 = r * (pab * c);
                y[rr][g*4+0] = (basev[g*4+0] + s0) * qt[g*4+0];
                y[rr][g*4+1] = (basev[g*4+1] + s1) * qt[g*4+1];
                y[rr][g*4+2] = (basev[g*4+2] + s2) * qt[g*4+2];
                y[rr][g*4+3] = (basev[g*4+3] + s3) * qt[g*4+3];
            }

            dct_fwd(y[rr][0], y[rr][1], y[rr][2], y[rr][3],
                    y[rr][4], y[rr][5], y[rr][6], y[rr][7]);
        }

        // exchange back -> column orientation
        #pragma unroll
        for (int rr = 0; rr < 4; rr++) {
            #pragma unroll
            for (int c = 0; c < 4; c++) {
                float send = hodd ? y[rr][c] : y[rr][4 + c];
                float recv = __shfl_xor_sync(0xFFFFFFFFu, send, 1);
                x[rr][c]     = hodd ? recv        : y[rr][c];
                x[rr + 4][c] = hodd ? y[rr][4 + c] : recv;
            }
        }

        // stage D: column inverse DCT (local)
        #pragma unroll
        for (int c = 0; c < 4; c++)
            dct_inv(x[0][c], x[1][c], x[2][c], x[3][c],
                    x[4][c], x[5][c], x[6][c], x[7][c]);

        // write back my 4 columns
        #pragma unroll
        for (int r = 0; r < 8; r++) {
            *(float4*)(blkp + r * 8 + half * 4) =
                make_float4(x[r][0], x[r][1], x[r][2], x[r][3]);
        }
    }
    __syncthreads();

    // ---- inverse color transform + store, float4 ----
    float* obase = out + (size_t)bimg * 3 * plane + (size_t)row0 * 512 + col0;
    for (int idx = t; idx < 512; idx += 192) {
        int rr = idx >> 6, c4 = idx & 63;
        int w = (c4 >> 1) * BLK_STRIDE + rr * 8 + (c4 & 1) * 4;
        float4 yv  = *(const float4*)&s_pix[w];
        float4 cbv = *(const float4*)&s_pix[CH_STRIDE + w];
        float4 crv = *(const float4*)&s_pix[2 * CH_STRIDE + w];
        float4 r4, g4, b4;
        {
            float y = yv.x, cb = cbv.x - 0.5f, cr = crv.x - 0.5f;
            r4.x = __saturatef(y + 1.402f * cr);
            g4.x = __saturatef(y - 0.344136f * cb - 0.714136f * cr);
            b4.x = __saturatef(y + 1.772f * cb);
        }
        {
            float y = yv.y, cb = cbv.y - 0.5f, cr = crv.y - 0.5f;
            r4.y = __saturatef(y + 1.402f * cr);
            g4.y = __saturatef(y - 0.344136f * cb - 0.714136f * cr);
            b4.y = __saturatef(y + 1.772f * cb);
        }
        {
            float y = yv.z, cb = cbv.z - 0.5f, cr = crv.z - 0.5f;
            r4.z = __saturatef(y + 1.402f * cr);
            g4.z = __saturatef(y - 0.344136f * cb - 0.714136f * cr);
            b4.z = __saturatef(y + 1.772f * cb);
        }
        {
            float y = yv.w, cb = cbv.w - 0.5f, cr = crv.w - 0.5f;
            r4.w = __saturatef(y + 1.402f * cr);
            g4.w = __saturatef(y - 0.344136f * cb - 0.714136f * cr);
            b4.w = __saturatef(y + 1.772f * cb);
        }
        size_t off = (size_t)rr * 512 + c4 * 4;
        *(float4*)(obase + off)             = r4;
        *(float4*)(obase + plane + off)     = g4;
        *(float4*)(obase + 2 * plane + off) = b4;
    }
}

extern "C" void kernel_launch(void* const* d_in, const int* in_sizes, int n_in,
                              void* d_out, int out_size) {
    const float* img = (const float*)d_in[0];
    const float* qy  = (const float*)d_in[1];
    const float* qc  = (const float*)d_in[2];
    float* out = (float*)d_out;
    (void)in_sizes; (void)n_in; (void)out_size;

    dim3 grid(512 / 256, 512 / 8, 8);   // (W bands, H bands, batch)
    dim3 block(192);
    djpeg_kernel<<<grid, block>>>(img, qy, qc, out);
}

// round 12
// speedup vs baseline: 1.3607x; 1.0449x over previous
#include <cuda_runtime.h>
#include <cuda_bf16.h>

// ---------------------------------------------------------------------------
// Differentiable JPEG, fused. A lane PAIR owns one 8x8 block (32 floats/thread).
// CTA = 192 threads = 96 channel-blocks = 32 spatial blocks x 3 channels.
// Tile = 8 rows x 256 cols. Grid = (2, 64, 8).
// R11: 5 CTAs/SM (<=68 regs), quant restructured in groups of 4 with exp2.
// ---------------------------------------------------------------------------

#define DA0 0.35355339059327373f
#define DC1 0.49039264020161522f
#define DC2 0.46193976625564337f
#define DC3 0.41573480615127262f
#define DC4 0.35355339059327373f
#define DC5 0.27778511650980114f
#define DC6 0.19134171618254492f
#define DC7 0.097545161008064166f

// forward: y = D x   (even/odd butterfly, 36 ops)
__device__ __forceinline__ void dct_fwd(float& x0, float& x1, float& x2, float& x3,
                                        float& x4, float& x5, float& x6, float& x7) {
    float e0 = x0 + x7, e1 = x1 + x6, e2 = x2 + x5, e3 = x3 + x4;
    float o0 = x0 - x7, o1 = x1 - x6, o2 = x2 - x5, o3 = x3 - x4;
    float ee0 = e0 + e3, ee1 = e1 + e2, eo0 = e0 - e3, eo1 = e1 - e2;
    float y0 = DA0 * (ee0 + ee1);
    float y4 = DC4 * (ee0 - ee1);
    float y2 = DC2 * eo0 + DC6 * eo1;
    float y6 = DC6 * eo0 - DC2 * eo1;
    float y1 = DC1 * o0 + DC3 * o1 + DC5 * o2 + DC7 * o3;
    float y3 = DC3 * o0 - DC7 * o1 - DC1 * o2 - DC5 * o3;
    float y5 = DC5 * o0 - DC1 * o1 + DC7 * o2 + DC3 * o3;
    float y7 = DC7 * o0 - DC5 * o1 + DC3 * o2 - DC1 * o3;
    x0 = y0; x1 = y1; x2 = y2; x3 = y3; x4 = y4; x5 = y5; x6 = y6; x7 = y7;
}

// inverse-type: z = D^T y  (36 ops)
__device__ __forceinline__ void dct_inv(float& y0, float& y1, float& y2, float& y3,
                                        float& y4, float& y5, float& y6, float& y7) {
    float t0 = DA0 * y0, t4 = DC4 * y4;
    float a = t0 + t4, b = t0 - t4;
    float c = DC2 * y2 + DC6 * y6;
    float d = DC6 * y2 - DC2 * y6;
    float E0 = a + c, E1 = b + d, E2 = b - d, E3 = a - c;
    float O0 = DC1 * y1 + DC3 * y3 + DC5 * y5 + DC7 * y7;
    float O1 = DC3 * y1 - DC7 * y3 - DC1 * y5 - DC5 * y7;
    float O2 = DC5 * y1 - DC1 * y3 + DC7 * y5 + DC3 * y7;
    float O3 = DC7 * y1 - DC5 * y3 + DC3 * y5 - DC1 * y7;
    y0 = E0 + O0; y7 = E0 - O0;
    y1 = E1 + O1; y6 = E1 - O1;
    y2 = E2 + O2; y5 = E2 - O2;
    y3 = E3 + O3; y4 = E3 - O3;
}

// soft_round * qt for 4 coefficients, one MUFU.RCP for all 4 sigmoids.
// sigmoid arg in exp2 domain: e^{-h} = 2^{fma(u, -50*log2e, c*50*log2e)}.
#define K2N  (-72.13475204444817f)
#define CK05 ( 36.067376022224085f)
#define CK15 (108.20212806667225f)
#define CLMP ( 28.853900817779268f)     // == |h| = 20

__device__ __forceinline__ void quant4(
    float& v0, float& v1, float& v2, float& v3,
    float rq0, float rq1, float rq2, float rq3,
    float qt0, float qt1, float qt2, float qt3)
{
    float b0, b1, b2, b3, t0, t1, t2, t3;
    {
        float f = v0 * rq0, kc = floorf(f - 0.5f), u = f - kc;
        bool hi = u > 1.0f; b0 = hi ? kc + 1.0f : kc;
        float a = fmaf(u, K2N, hi ? CK15 : CK05);
        a = fminf(fmaxf(a, -CLMP), CLMP);
        float e; asm("ex2.approx.ftz.f32 %0, %1;" : "=f"(e) : "f"(a));
        t0 = 1.0f + e;
    }
    {
        float f = v1 * rq1, kc = floorf(f - 0.5f), u = f - kc;
        bool hi = u > 1.0f; b1 = hi ? kc + 1.0f : kc;
        float a = fmaf(u, K2N, hi ? CK15 : CK05);
        a = fminf(fmaxf(a, -CLMP), CLMP);
        float e; asm("ex2.approx.ftz.f32 %0, %1;" : "=f"(e) : "f"(a));
        t1 = 1.0f + e;
    }
    {
        float f = v2 * rq2, kc = floorf(f - 0.5f), u = f - kc;
        bool hi = u > 1.0f; b2 = hi ? kc + 1.0f : kc;
        float a = fmaf(u, K2N, hi ? CK15 : CK05);
        a = fminf(fmaxf(a, -CLMP), CLMP);
        float e; asm("ex2.approx.ftz.f32 %0, %1;" : "=f"(e) : "f"(a));
        t2 = 1.0f + e;
    }
    {
        float f = v3 * rq3, kc = floorf(f - 0.5f), u = f - kc;
        bool hi = u > 1.0f; b3 = hi ? kc + 1.0f : kc;
        float a = fmaf(u, K2N, hi ? CK15 : CK05);
        a = fminf(fmaxf(a, -CLMP), CLMP);
        float e; asm("ex2.approx.ftz.f32 %0, %1;" : "=f"(e) : "f"(a));
        t3 = 1.0f + e;
    }
    float pab = t0 * t1, pcd = t2 * t3;
    float r = __fdividef(1.0f, pab * pcd);
    v0 = (b0 + r * (t1 * pcd)) * qt0;
    v1 = (b1 + r * (t0 * pcd)) * qt1;
    v2 = (b2 + r * (pab * t3)) * qt2;
    v3 = (b3 + r * (pab * t2)) * qt3;
}

// block-major padded smem: [ch][block 0..31][72 words]; word = bc*72 + r*8 + j
#define BLK_STRIDE 72
#define CH_STRIDE  (32 * BLK_STRIDE)

__global__ void __launch_bounds__(192, 5)
djpeg_kernel(const float* __restrict__ img,
             const float* __restrict__ qy,
             const float* __restrict__ qc,
             float* __restrict__ out)
{
    __shared__ float s_pix[3 * CH_STRIDE];
    __shared__ float s_qt[2][64];
    __shared__ float s_rq[2][64];

    const int t    = threadIdx.x;
    const int bimg = blockIdx.z;
    const int row0 = blockIdx.y << 3;    // 8-row band
    const int col0 = blockIdx.x << 8;    // 256-col band

    // quant tables: clip to [2,15], reciprocals
    if (t < 128) {
        int chq = t >> 6, idx = t & 63;
        float v = chq ? qc[idx] : qy[idx];
        v = fminf(fmaxf(v, 2.0f), 15.0f);
        s_qt[chq][idx] = v;
        s_rq[chq][idx] = 1.0f / v;
    }

    const size_t plane = 512 * 512;
    const float* base = img + (size_t)bimg * 3 * plane + (size_t)row0 * 512 + col0;

    // ---- load + forward color transform, float4, into block-major smem ----
    for (int idx = t; idx < 512; idx += 192) {
        int rr = idx >> 6, c4 = idx & 63;
        const float4 r4 = *(const float4*)(base + (size_t)rr * 512 + c4 * 4);
        const float4 g4 = *(const float4*)(base + plane + (size_t)rr * 512 + c4 * 4);
        const float4 b4 = *(const float4*)(base + 2 * plane + (size_t)rr * 512 + c4 * 4);
        float4 yv, cbv, crv;
        {
            float r = __saturatef(r4.x), g = __saturatef(g4.x), bl = __saturatef(b4.x);
            yv.x  =  0.299f * r + 0.587f * g + 0.114f * bl;
            cbv.x = -0.168736f * r - 0.331264f * g + 0.5f * bl + 0.5f;
            crv.x =  0.5f * r - 0.418688f * g - 0.081312f * bl + 0.5f;
        }
        {
            float r = __saturatef(r4.y), g = __saturatef(g4.y), bl = __saturatef(b4.y);
            yv.y  =  0.299f * r + 0.587f * g + 0.114f * bl;
            cbv.y = -0.168736f * r - 0.331264f * g + 0.5f * bl + 0.5f;
            crv.y =  0.5f * r - 0.418688f * g - 0.081312f * bl + 0.5f;
        }
        {
            float r = __saturatef(r4.z), g = __saturatef(g4.z), bl = __saturatef(b4.z);
            yv.z  =  0.299f * r + 0.587f * g + 0.114f * bl;
            cbv.z = -0.168736f * r - 0.331264f * g + 0.5f * bl + 0.5f;
            crv.z =  0.5f * r - 0.418688f * g - 0.081312f * bl + 0.5f;
        }
        {
            float r = __saturatef(r4.w), g = __saturatef(g4.w), bl = __saturatef(b4.w);
            yv.w  =  0.299f * r + 0.587f * g + 0.114f * bl;
            cbv.w = -0.168736f * r - 0.331264f * g + 0.5f * bl + 0.5f;
            crv.w =  0.5f * r - 0.418688f * g - 0.081312f * bl + 0.5f;
        }
        int w = (c4 >> 1) * BLK_STRIDE + rr * 8 + (c4 & 1) * 4;  // block-major word
        *(float4*)&s_pix[w]                 = yv;
        *(float4*)&s_pix[CH_STRIDE + w]     = cbv;
        *(float4*)&s_pix[2 * CH_STRIDE + w] = crv;
    }
    __syncthreads();

    // ---- pair-of-threads per 8x8 block ----
    {
        const int pb   = t >> 1;        // channel-block 0..95
        const int half = t & 1;         // which 4-col / 4-row half
        const int ch   = pb >> 5;       // 0..2
        const int bc   = pb & 31;
        const int qs   = (ch == 0) ? 0 : 1;
        const bool hodd = (half != 0);
        float* blkp = &s_pix[ch * CH_STRIDE + bc * BLK_STRIDE];

        // load my 4 columns (global cols half*4 .. half*4+3), all 8 rows
        float x[8][4];
        #pragma unroll
        for (int r = 0; r < 8; r++) {
            float4 v = *(const float4*)(blkp + r * 8 + half * 4);
            x[r][0] = v.x; x[r][1] = v.y; x[r][2] = v.z; x[r][3] = v.w;
        }

        // stage A: column forward DCT (local)
        #pragma unroll
        for (int c = 0; c < 4; c++)
            dct_fwd(x[0][c], x[1][c], x[2][c], x[3][c],
                    x[4][c], x[5][c], x[6][c], x[7][c]);

        // exchange -> row orientation: I own global rows half*4..half*4+3, all 8 cols
        float y[4][8];
        #pragma unroll
        for (int rr = 0; rr < 4; rr++) {
            #pragma unroll
            for (int c = 0; c < 4; c++) {
                float send = hodd ? x[rr][c] : x[rr + 4][c];
                float recv = __shfl_xor_sync(0xFFFFFFFFu, send, 1);
                y[rr][c]     = hodd ? recv        : x[rr][c];
                y[rr][4 + c] = hodd ? x[rr + 4][c] : recv;
            }
        }

        // row stages: coef = M*D (D^T-type), quant, N = Q*D^T (D-type)
        const int ibase = half * 4;
        #pragma unroll
        for (int rr = 0; rr < 4; rr++) {
            dct_inv(y[rr][0], y[rr][1], y[rr][2], y[rr][3],
                    y[rr][4], y[rr][5], y[rr][6], y[rr][7]);

            const int i = ibase + rr;
            float4 rqlo = *(const float4*)&s_rq[qs][i * 8];
            float4 rqhi = *(const float4*)&s_rq[qs][i * 8 + 4];
            float4 qtlo = *(const float4*)&s_qt[qs][i * 8];
            float4 qthi = *(const float4*)&s_qt[qs][i * 8 + 4];

            quant4(y[rr][0], y[rr][1], y[rr][2], y[rr][3],
                   rqlo.x, rqlo.y, rqlo.z, rqlo.w,
                   qtlo.x, qtlo.y, qtlo.z, qtlo.w);
            quant4(y[rr][4], y[rr][5], y[rr][6], y[rr][7],
                   rqhi.x, rqhi.y, rqhi.z, rqhi.w,
                   qthi.x, qthi.y, qthi.z, qthi.w);

            dct_fwd(y[rr][0], y[rr][1], y[rr][2], y[rr][3],
                    y[rr][4], y[rr][5], y[rr][6], y[rr][7]);
        }

        // exchange back -> column orientation
        #pragma unroll
        for (int rr = 0; rr < 4; rr++) {
            #pragma unroll
            for (int c = 0; c < 4; c++) {
                float send = hodd ? y[rr][c] : y[rr][4 + c];
                float recv = __shfl_xor_sync(0xFFFFFFFFu, send, 1);
                x[rr][c]     = hodd ? recv        : y[rr][c];
                x[rr + 4][c] = hodd ? y[rr][4 + c] : recv;
            }
        }

        // stage D: column inverse DCT (local)
        #pragma unroll
        for (int c = 0; c < 4; c++)
            dct_inv(x[0][c], x[1][c], x[2][c], x[3][c],
                    x[4][c], x[5][c], x[6][c], x[7][c]);

        // write back my 4 columns
        #pragma unroll
        for (int r = 0; r < 8; r++) {
            *(float4*)(blkp + r * 8 + half * 4) =
                make_float4(x[r][0], x[r][1], x[r][2], x[r][3]);
        }
    }
    __syncthreads();

    // ---- inverse color transform + store, float4 ----
    float* obase = out + (size_t)bimg * 3 * plane + (size_t)row0 * 512 + col0;
    for (int idx = t; idx < 512; idx += 192) {
        int rr = idx >> 6, c4 = idx & 63;
        int w = (c4 >> 1) * BLK_STRIDE + rr * 8 + (c4 & 1) * 4;
        float4 yv  = *(const float4*)&s_pix[w];
        float4 cbv = *(const float4*)&s_pix[CH_STRIDE + w];
        float4 crv = *(const float4*)&s_pix[2 * CH_STRIDE + w];
        float4 r4, g4, b4;
        {
            float y = yv.x, cb = cbv.x - 0.5f, cr = crv.x - 0.5f;
            r4.x = __saturatef(y + 1.402f * cr);
            g4.x = __saturatef(y - 0.344136f * cb - 0.714136f * cr);
            b4.x = __saturatef(y + 1.772f * cb);
        }
        {
            float y = yv.y, cb = cbv.y - 0.5f, cr = crv.y - 0.5f;
            r4.y = __saturatef(y + 1.402f * cr);
            g4.y = __saturatef(y - 0.344136f * cb - 0.714136f * cr);
            b4.y = __saturatef(y + 1.772f * cb);
        }
        {
            float y = yv.z, cb = cbv.z - 0.5f, cr = crv.z - 0.5f;
            r4.z = __saturatef(y + 1.402f * cr);
            g4.z = __saturatef(y - 0.344136f * cb - 0.714136f * cr);
            b4.z = __saturatef(y + 1.772f * cb);
        }
        {
            float y = yv.w, cb = cbv.w - 0.5f, cr = crv.w - 0.5f;
            r4.w = __saturatef(y + 1.402f * cr);
            g4.w = __saturatef(y - 0.344136f * cb - 0.714136f * cr);
            b4.w = __saturatef(y + 1.772f * cb);
        }
        size_t off = (size_t)rr * 512 + c4 * 4;
        *(float4*)(obase + off)             = r4;
        *(float4*)(obase + plane + off)     = g4;
        *(float4*)(obase + 2 * plane + off) = b4;
    }
}

extern "C" void kernel_launch(void* const* d_in, const int* in_sizes, int n_in,
                              void* d_out, int out_size) {
    const float* img = (const float*)d_in[0];
    const float* qy  = (const float*)d_in[1];
    const float* qc  = (const float*)d_in[2];
    float* out = (float*)d_out;
    (void)in_sizes; (void)n_in; (void)out_size;

    dim3 grid(512 / 256, 512 / 8, 8);   // (W bands, H bands, batch)
    dim3 block(192);
    djpeg_kernel<<<grid, block>>>(img, qy, qc, out);
}

// round 17
// speedup vs baseline: 1.3633x; 1.0019x over previous
#include <cuda_runtime.h>
#include <cuda_bf16.h>

// ---------------------------------------------------------------------------
// Differentiable JPEG, fused. A lane PAIR owns one 8x8 block (32 floats/thread).
// R13: CTA halved to 96 threads (8x128 tile, 16 blocks x 3 ch) so 10 CTAs/SM
// interleave their load/compute/store phases. Grid = (4, 64, 8).
// ---------------------------------------------------------------------------

#define DA0 0.35355339059327373f
#define DC1 0.49039264020161522f
#define DC2 0.46193976625564337f
#define DC3 0.41573480615127262f
#define DC4 0.35355339059327373f
#define DC5 0.27778511650980114f
#define DC6 0.19134171618254492f
#define DC7 0.097545161008064166f

// forward: y = D x   (even/odd butterfly, 36 ops)
__device__ __forceinline__ void dct_fwd(float& x0, float& x1, float& x2, float& x3,
                                        float& x4, float& x5, float& x6, float& x7) {
    float e0 = x0 + x7, e1 = x1 + x6, e2 = x2 + x5, e3 = x3 + x4;
    float o0 = x0 - x7, o1 = x1 - x6, o2 = x2 - x5, o3 = x3 - x4;
    float ee0 = e0 + e3, ee1 = e1 + e2, eo0 = e0 - e3, eo1 = e1 - e2;
    float y0 = DA0 * (ee0 + ee1);
    float y4 = DC4 * (ee0 - ee1);
    float y2 = DC2 * eo0 + DC6 * eo1;
    float y6 = DC6 * eo0 - DC2 * eo1;
    float y1 = DC1 * o0 + DC3 * o1 + DC5 * o2 + DC7 * o3;
    float y3 = DC3 * o0 - DC7 * o1 - DC1 * o2 - DC5 * o3;
    float y5 = DC5 * o0 - DC1 * o1 + DC7 * o2 + DC3 * o3;
    float y7 = DC7 * o0 - DC5 * o1 + DC3 * o2 - DC1 * o3;
    x0 = y0; x1 = y1; x2 = y2; x3 = y3; x4 = y4; x5 = y5; x6 = y6; x7 = y7;
}

// inverse-type: z = D^T y  (36 ops)
__device__ __forceinline__ void dct_inv(float& y0, float& y1, float& y2, float& y3,
                                        float& y4, float& y5, float& y6, float& y7) {
    float t0 = DA0 * y0, t4 = DC4 * y4;
    float a = t0 + t4, b = t0 - t4;
    float c = DC2 * y2 + DC6 * y6;
    float d = DC6 * y2 - DC2 * y6;
    float E0 = a + c, E1 = b + d, E2 = b - d, E3 = a - c;
    float O0 = DC1 * y1 + DC3 * y3 + DC5 * y5 + DC7 * y7;
    float O1 = DC3 * y1 - DC7 * y3 - DC1 * y5 - DC5 * y7;
    float O2 = DC5 * y1 - DC1 * y3 + DC7 * y5 + DC3 * y7;
    float O3 = DC7 * y1 - DC5 * y3 + DC3 * y5 - DC1 * y7;
    y0 = E0 + O0; y7 = E0 - O0;
    y1 = E1 + O1; y6 = E1 - O1;
    y2 = E2 + O2; y5 = E2 - O2;
    y3 = E3 + O3; y4 = E3 - O3;
}

// soft_round * qt for 4 coefficients, one MUFU.RCP for all 4 sigmoids.
#define K2N  (-72.13475204444817f)
#define CK05 ( 36.067376022224085f)
#define CK15 (108.20212806667225f)
#define CLMP ( 28.853900817779268f)     // == |h| = 20

__device__ __forceinline__ void quant4(
    float& v0, float& v1, float& v2, float& v3,
    float rq0, float rq1, float rq2, float rq3,
    float qt0, float qt1, float qt2, float qt3)
{
    float b0, b1, b2, b3, t0, t1, t2, t3;
    {
        float f = v0 * rq0, kc = floorf(f - 0.5f), u = f - kc;
        bool hi = u > 1.0f; b0 = hi ? kc + 1.0f : kc;
        float a = fmaf(u, K2N, hi ? CK15 : CK05);
        a = fminf(fmaxf(a, -CLMP), CLMP);
        float e; asm("ex2.approx.ftz.f32 %0, %1;" : "=f"(e) : "f"(a));
        t0 = 1.0f + e;
    }
    {
        float f = v1 * rq1, kc = floorf(f - 0.5f), u = f - kc;
        bool hi = u > 1.0f; b1 = hi ? kc + 1.0f : kc;
        float a = fmaf(u, K2N, hi ? CK15 : CK05);
        a = fminf(fmaxf(a, -CLMP), CLMP);
        float e; asm("ex2.approx.ftz.f32 %0, %1;" : "=f"(e) : "f"(a));
        t1 = 1.0f + e;
    }
    {
        float f = v2 * rq2, kc = floorf(f - 0.5f), u = f - kc;
        bool hi = u > 1.0f; b2 = hi ? kc + 1.0f : kc;
        float a = fmaf(u, K2N, hi ? CK15 : CK05);
        a = fminf(fmaxf(a, -CLMP), CLMP);
        float e; asm("ex2.approx.ftz.f32 %0, %1;" : "=f"(e) : "f"(a));
        t2 = 1.0f + e;
    }
    {
        float f = v3 * rq3, kc = floorf(f - 0.5f), u = f - kc;
        bool hi = u > 1.0f; b3 = hi ? kc + 1.0f : kc;
        float a = fmaf(u, K2N, hi ? CK15 : CK05);
        a = fminf(fmaxf(a, -CLMP), CLMP);
        float e; asm("ex2.approx.ftz.f32 %0, %1;" : "=f"(e) : "f"(a));
        t3 = 1.0f + e;
    }
    float pab = t0 * t1, pcd = t2 * t3;
    float r = __fdividef(1.0f, pab * pcd);
    v0 = (b0 + r * (t1 * pcd)) * qt0;
    v1 = (b1 + r * (t0 * pcd)) * qt1;
    v2 = (b2 + r * (pab * t3)) * qt2;
    v3 = (b3 + r * (pab * t2)) * qt3;
}

// block-major padded smem: [ch][block 0..15][72 words]; word = bc*72 + r*8 + j
#define BLK_STRIDE 72
#define NBLK       16
#define CH_STRIDE  (NBLK * BLK_STRIDE)

__global__ void __launch_bounds__(96, 10)
djpeg_kernel(const float* __restrict__ img,
             const float* __restrict__ qy,
             const float* __restrict__ qc,
             float* __restrict__ out)
{
    __shared__ float s_pix[3 * CH_STRIDE];
    __shared__ float s_qt[2][64];
    __shared__ float s_rq[2][64];

    const int t    = threadIdx.x;
    const int bimg = blockIdx.z;
    const int row0 = blockIdx.y << 3;    // 8-row band
    const int col0 = blockIdx.x << 7;    // 128-col band

    // quant tables: clip to [2,15], reciprocals
    for (int i = t; i < 128; i += 96) {
        int chq = i >> 6, idx = i & 63;
        float v = chq ? qc[idx] : qy[idx];
        v = fminf(fmaxf(v, 2.0f), 15.0f);
        s_qt[chq][idx] = v;
        s_rq[chq][idx] = 1.0f / v;
    }

    const size_t plane = 512 * 512;
    const float* base = img + (size_t)bimg * 3 * plane + (size_t)row0 * 512 + col0;

    // ---- load + forward color transform, float4, into block-major smem ----
    // 256 spatial float4s in tile (8 rows x 32 f4)
    for (int idx = t; idx < 256; idx += 96) {
        int rr = idx >> 5, c4 = idx & 31;
        const float4 r4 = *(const float4*)(base + (size_t)rr * 512 + c4 * 4);
        const float4 g4 = *(const float4*)(base + plane + (size_t)rr * 512 + c4 * 4);
        const float4 b4 = *(const float4*)(base + 2 * plane + (size_t)rr * 512 + c4 * 4);
        float4 yv, cbv, crv;
        {
            float r = __saturatef(r4.x), g = __saturatef(g4.x), bl = __saturatef(b4.x);
            yv.x  =  0.299f * r + 0.587f * g + 0.114f * bl;
            cbv.x = -0.168736f * r - 0.331264f * g + 0.5f * bl + 0.5f;
            crv.x =  0.5f * r - 0.418688f * g - 0.081312f * bl + 0.5f;
        }
        {
            float r = __saturatef(r4.y), g = __saturatef(g4.y), bl = __saturatef(b4.y);
            yv.y  =  0.299f * r + 0.587f * g + 0.114f * bl;
            cbv.y = -0.168736f * r - 0.331264f * g + 0.5f * bl + 0.5f;
            crv.y =  0.5f * r - 0.418688f * g - 0.081312f * bl + 0.5f;
        }
        {
            float r = __saturatef(r4.z), g = __saturatef(g4.z), bl = __saturatef(b4.z);
            yv.z  =  0.299f * r + 0.587f * g + 0.114f * bl;
            cbv.z = -0.168736f * r - 0.331264f * g + 0.5f * bl + 0.5f;
            crv.z =  0.5f * r - 0.418688f * g - 0.081312f * bl + 0.5f;
        }
        {
            float r = __saturatef(r4.w), g = __saturatef(g4.w), bl = __saturatef(b4.w);
            yv.w  =  0.299f * r + 0.587f * g + 0.114f * bl;
            cbv.w = -0.168736f * r - 0.331264f * g + 0.5f * bl + 0.5f;
            crv.w =  0.5f * r - 0.418688f * g - 0.081312f * bl + 0.5f;
        }
        int w = (c4 >> 1) * BLK_STRIDE + rr * 8 + (c4 & 1) * 4;  // block-major word
        *(float4*)&s_pix[w]                 = yv;
        *(float4*)&s_pix[CH_STRIDE + w]     = cbv;
        *(float4*)&s_pix[2 * CH_STRIDE + w] = crv;
    }
    __syncthreads();

    // ---- pair-of-threads per 8x8 block ----
    {
        const int pb   = t >> 1;        // channel-block 0..47
        const int half = t & 1;         // which 4-col / 4-row half
        const int ch   = pb >> 4;       // 0..2
        const int bc   = pb & 15;
        const int qs   = (ch == 0) ? 0 : 1;
        const bool hodd = (half != 0);
        float* blkp = &s_pix[ch * CH_STRIDE + bc * BLK_STRIDE];

        // load my 4 columns (global cols half*4 .. half*4+3), all 8 rows
        float x[8][4];
        #pragma unroll
        for (int r = 0; r < 8; r++) {
            float4 v = *(const float4*)(blkp + r * 8 + half * 4);
            x[r][0] = v.x; x[r][1] = v.y; x[r][2] = v.z; x[r][3] = v.w;
        }

        // stage A: column forward DCT (local)
        #pragma unroll
        for (int c = 0; c < 4; c++)
            dct_fwd(x[0][c], x[1][c], x[2][c], x[3][c],
                    x[4][c], x[5][c], x[6][c], x[7][c]);

        // exchange -> row orientation: I own global rows half*4..half*4+3, all 8 cols
        float y[4][8];
        #pragma unroll
        for (int rr = 0; rr < 4; rr++) {
            #pragma unroll
            for (int c = 0; c < 4; c++) {
                float send = hodd ? x[rr][c] : x[rr + 4][c];
                float recv = __shfl_xor_sync(0xFFFFFFFFu, send, 1);
                y[rr][c]     = hodd ? recv        : x[rr][c];
                y[rr][4 + c] = hodd ? x[rr + 4][c] : recv;
            }
        }

        // row stages: coef = M*D (D^T-type), quant, N = Q*D^T (D-type)
        const int ibase = half * 4;
        #pragma unroll
        for (int rr = 0; rr < 4; rr++) {
            dct_inv(y[rr][0], y[rr][1], y[rr][2], y[rr][3],
                    y[rr][4], y[rr][5], y[rr][6], y[rr][7]);

            const int i = ibase + rr;
            float4 rqlo = *(const float4*)&s_rq[qs][i * 8];
            float4 rqhi = *(const float4*)&s_rq[qs][i * 8 + 4];
            float4 qtlo = *(const float4*)&s_qt[qs][i * 8];
            float4 qthi = *(const float4*)&s_qt[qs][i * 8 + 4];

            quant4(y[rr][0], y[rr][1], y[rr][2], y[rr][3],
                   rqlo.x, rqlo.y, rqlo.z, rqlo.w,
                   qtlo.x, qtlo.y, qtlo.z, qtlo.w);
            quant4(y[rr][4], y[rr][5], y[rr][6], y[rr][7],
                   rqhi.x, rqhi.y, rqhi.z, rqhi.w,
                   qthi.x, qthi.y, qthi.z, qthi.w);

            dct_fwd(y[rr][0], y[rr][1], y[rr][2], y[rr][3],
                    y[rr][4], y[rr][5], y[rr][6], y[rr][7]);
        }

        // exchange back -> column orientation
        #pragma unroll
        for (int rr = 0; rr < 4; rr++) {
            #pragma unroll
            for (int c = 0; c < 4; c++) {
                float send = hodd ? y[rr][c] : y[rr][4 + c];
                float recv = __shfl_xor_sync(0xFFFFFFFFu, send, 1);
                x[rr][c]     = hodd ? recv        : y[rr][c];
                x[rr + 4][c] = hodd ? y[rr][4 + c] : recv;
            }
        }

        // stage D: column inverse DCT (local)
        #pragma unroll
        for (int c = 0; c < 4; c++)
            dct_inv(x[0][c], x[1][c], x[2][c], x[3][c],
                    x[4][c], x[5][c], x[6][c], x[7][c]);

        // write back my 4 columns
        #pragma unroll
        for (int r = 0; r < 8; r++) {
            *(float4*)(blkp + r * 8 + half * 4) =
                make_float4(x[r][0], x[r][1], x[r][2], x[r][3]);
        }
    }
    __syncthreads();

    // ---- inverse color transform + store, float4 ----
    float* obase = out + (size_t)bimg * 3 * plane + (size_t)row0 * 512 + col0;
    for (int idx = t; idx < 256; idx += 96) {
        int rr = idx >> 5, c4 = idx & 31;
        int w = (c4 >> 1) * BLK_STRIDE + rr * 8 + (c4 & 1) * 4;
        float4 yv  = *(const float4*)&s_pix[w];
        float4 cbv = *(const float4*)&s_pix[CH_STRIDE + w];
        float4 crv = *(const float4*)&s_pix[2 * CH_STRIDE + w];
        float4 r4, g4, b4;
        {
            float y = yv.x, cb = cbv.x - 0.5f, cr = crv.x - 0.5f;
            r4.x = __saturatef(y + 1.402f * cr);
            g4.x = __saturatef(y - 0.344136f * cb - 0.714136f * cr);
            b4.x = __saturatef(y + 1.772f * cb);
        }
        {
            float y = yv.y, cb = cbv.y - 0.5f, cr = crv.y - 0.5f;
            r4.y = __saturatef(y + 1.402f * cr);
            g4.y = __saturatef(y - 0.344136f * cb - 0.714136f * cr);
            b4.y = __saturatef(y + 1.772f * cb);
        }
        {
            float y = yv.z, cb = cbv.z - 0.5f, cr = crv.z - 0.5f;
            r4.z = __saturatef(y + 1.402f * cr);
            g4.z = __saturatef(y - 0.344136f * cb - 0.714136f * cr);
            b4.z = __saturatef(y + 1.772f * cb);
        }
        {
            float y = yv.w, cb = cbv.w - 0.5f, cr = crv.w - 0.5f;
            r4.w = __saturatef(y + 1.402f * cr);
            g4.w = __saturatef(y - 0.344136f * cb - 0.714136f * cr);
            b4.w = __saturatef(y + 1.772f * cb);
        }
        size_t off = (size_t)rr * 512 + c4 * 4;
        *(float4*)(obase + off)             = r4;
        *(float4*)(obase + plane + off)     = g4;
        *(float4*)(obase + 2 * plane + off) = b4;
    }
}

extern "C" void kernel_launch(void* const* d_in, const int* in_sizes, int n_in,
                              void* d_out, int out_size) {
    const float* img = (const float*)d_in[0];
    const float* qy  = (const float*)d_in[1];
    const float* qc  = (const float*)d_in[2];
    float* out = (float*)d_out;
    (void)in_sizes; (void)n_in; (void)out_size;

    dim3 grid(512 / 128, 512 / 8, 8);   // (W bands, H bands, batch)
    dim3 block(96);
    djpeg_kernel<<<grid, block>>>(img, qy, qc, out);
}